// round 14
// baseline (speedup 1.0000x reference)
#include <cuda_runtime.h>
#include <cuda_fp16.h>
#include <cstdint>

// Problem constants: B=8, C=128, H=W=64, O=128, 3x3, stride 1, pad 1, dil 1
#define BB 8
#define CC 128
#define HH 64
#define WW 64
#define OO 128
#define KTAP 9
#define HW (HH*WW)          // 4096
#define CK (CC*KTAP)        // 1152
#define NCHUNK 18           // CK / 64

// Scratch
__device__ __half g_xTh[BB*HH*WW*CC];   // [b][h][w][c] fp16, 8 MB
// B in fragment-major layout: [ch(18)][half(2)][s(4)][p(4)][lane(32)] x uint4
__device__ uint4 g_wbF[NCHUNK*1024];    // 288 KB

// ---------------------------------------------------------------------------
// SMEM: A tile 64 rows x 144B x 2 stages + bilinear tables [9][64][4]
// ---------------------------------------------------------------------------
#define AROW 144
#define ATILE (64*AROW)             // 9216
#define A_OFF(st) ((st)*ATILE)
#define SM_IDX (2*ATILE)            // 18432
#define SM_WT  (SM_IDX + 9*64*4*4)  // 27648
#define SMEM_TOTAL (SM_WT + 9*64*4*4)   // 36864 -> 3 CTAs/SM
#define EROW 68                     // epilogue smem row pitch (floats)

__device__ __forceinline__ uint32_t smem_u32(const void* p) {
    uint32_t a;
    asm("{ .reg .u64 t; cvta.to.shared.u64 t, %1; cvt.u32.u64 %0, t; }" : "=r"(a) : "l"(p));
    return a;
}
__device__ __forceinline__ void ldsm4(uint32_t addr, uint32_t* r) {
    asm volatile("ldmatrix.sync.aligned.m8n8.x4.shared.b16 {%0,%1,%2,%3}, [%4];"
                 : "=r"(r[0]), "=r"(r[1]), "=r"(r[2]), "=r"(r[3]) : "r"(addr));
}
__device__ __forceinline__ void mma16816(float* d, const uint32_t* a, const uint32_t* b) {
    asm volatile("mma.sync.aligned.m16n8k16.row.col.f32.f16.f16.f32 "
                 "{%0,%1,%2,%3}, {%4,%5,%6,%7}, {%8,%9}, {%0,%1,%2,%3};"
                 : "+f"(d[0]), "+f"(d[1]), "+f"(d[2]), "+f"(d[3])
                 : "r"(a[0]), "r"(a[1]), "r"(a[2]), "r"(a[3]), "r"(b[0]), "r"(b[1]));
}
#define PAIR_BAR(pid) asm volatile("bar.sync %0, 64;" :: "r"(1 + (pid)) : "memory")

// ---------------------------------------------------------------------------
// Kernel 1 (fused prep): blockIdx.x < 128 -> xpose tile; else -> wprep frag
// grid (128+5, 2, 8), block (32,8)
// ---------------------------------------------------------------------------
__global__ void prep_kernel(const float* __restrict__ x, const float* __restrict__ w) {
    if (blockIdx.x < 128) {
        __shared__ float tile[64][33];
        int b   = blockIdx.z;
        int hw0 = blockIdx.x * 32;
        int c0  = blockIdx.y * 64;
        const float* xb = x + (size_t)b * CC * HW;
#pragma unroll
        for (int j = 0; j < 64; j += 8)
            tile[threadIdx.y + j][threadIdx.x] =
                xb[(size_t)(c0 + threadIdx.y + j) * HW + hw0 + threadIdx.x];
        __syncthreads();
        __half* ob = g_xTh + (size_t)b * HW * CC + c0;
#pragma unroll
        for (int j = 0; j < 32; j += 8) {
            int row = threadIdx.y + j;
            __half2 h = __floats2half2_rn(tile[threadIdx.x * 2][row],
                                          tile[threadIdx.x * 2 + 1][row]);
            *reinterpret_cast<__half2*>(ob + (size_t)(hw0 + row) * CC + threadIdx.x * 2) = h;
        }
    } else {
        // weight [O,C,3,3] -> fragment-major B: one uint4 (8 fp16) per thread
        int slice = (blockIdx.x - 128) * 16 + blockIdx.z * 2 + blockIdx.y;  // 0..79
        int idx = slice * 256 + threadIdx.y * 32 + threadIdx.x;
        if (idx >= NCHUNK * 1024) return;
        int lane = idx & 31;
        int p    = (idx >> 5) & 3;
        int s    = (idx >> 7) & 3;
        int h    = (idx >> 9) & 1;
        int ch   = idx >> 10;
        int tap  = ch >> 1;
        int cbase = (ch & 1) << 6;
        uint32_t regs[4];
#pragma unroll
        for (int j = 0; j < 4; j++) {
            int o  = h * 64 + p * 16 + (lane >> 2) + ((j >> 1) << 3);
            int k0 = s * 16 + ((lane & 3) << 1) + ((j & 1) << 3);
            float v0 = w[(size_t)o * CK + (cbase + k0) * KTAP + tap];
            float v1 = w[(size_t)o * CK + (cbase + k0 + 1) * KTAP + tap];
            __half2 hh = __floats2half2_rn(v0, v1);
            regs[j] = *reinterpret_cast<uint32_t*>(&hh);
        }
        g_wbF[idx] = make_uint4(regs[0], regs[1], regs[2], regs[3]);
    }
}

// ---------------------------------------------------------------------------
// Kernel 2: fused gather + mma.sync fp16 GEMM
// grid = 512 (one CTA per output row: 64 spatial x 128 out), 256 threads
// warp tile 16x64 -> 32 accs -> 3 CTAs/SM
// ---------------------------------------------------------------------------
__global__ void __launch_bounds__(256, 3) dcn_mma_kernel(
    const float* __restrict__ offset,
    const float* __restrict__ bias,
    float* __restrict__ out)
{
    extern __shared__ char smem[];
    const uint32_t sb = smem_u32(smem);
    const int tid  = threadIdx.x;
    const int wid  = tid >> 5;
    const int lane = tid & 31;
    const int pair = wid >> 1;
    const int b    = blockIdx.x >> 6;
    const int ho   = blockIdx.x & 63;
    const int hw0  = ho * 64;

    int*   sIdx = reinterpret_cast<int*>(smem + SM_IDX);
    float* sWt  = reinterpret_cast<float*>(smem + SM_WT);

    // ---- precompute bilinear params for all (tap, m), m = wo 0..63 ----
    for (int p = tid; p < KTAP * 64; p += 256) {
        int m = p & 63;
        int k = p >> 6;
        float dy = offset[(((size_t)b * 18 + 2 * k    ) * 64 + ho) * 64 + m];
        float dx = offset[(((size_t)b * 18 + 2 * k + 1) * 64 + ho) * 64 + m];
        float py = (float)(ho - 1 + k / 3) + dy;
        float px = (float)(m  - 1 + k % 3) + dx;
        float y0f = floorf(py), x0f = floorf(px);
        int   y0 = (int)y0f,    x0 = (int)x0f;
        float ly = py - y0f, lx = px - x0f;
        float w4[4] = { (1.f - ly) * (1.f - lx), (1.f - ly) * lx,
                        ly * (1.f - lx),         ly * lx };
#pragma unroll
        for (int i = 0; i < 4; i++) {
            int yy = y0 + (i >> 1);
            int xx = x0 + (i & 1);
            bool v = (yy >= 0) & (yy < HH) & (xx >= 0) & (xx < WW);
            sWt[p * 4 + i]  = v ? w4[i] : 0.f;
            sIdx[p * 4 + i] = v ? (((b * HH + yy) * WW + xx) * CC) : 0;
        }
    }
    __syncthreads();

    // warp-coalesced fp16 bilinear gather: warp owns 8 rows per chunk
    const int sub4 = lane >> 3;
    const int l8   = lane & 7;
    const int rbase = (wid >> 1) * 16 + (wid & 1) * 8;
    auto gatherA = [&](int st, int ch) {
        const int k   = ch >> 1;
        const int cc  = ((ch & 1) << 6) + (l8 << 3);
        char* base = smem + A_OFF(st);
#pragma unroll
        for (int p = 0; p < 2; p++) {
            int m = rbase + (p << 2) + sub4;
            const int4   id = *reinterpret_cast<const int4*>(sIdx + ((k << 6) + m) * 4);
            const float4 wt = *reinterpret_cast<const float4*>(sWt + ((k << 6) + m) * 4);
            uint4 r0 = *reinterpret_cast<const uint4*>(g_xTh + id.x + cc);
            uint4 r1 = *reinterpret_cast<const uint4*>(g_xTh + id.y + cc);
            uint4 r2 = *reinterpret_cast<const uint4*>(g_xTh + id.z + cc);
            uint4 r3 = *reinterpret_cast<const uint4*>(g_xTh + id.w + cc);
            uint4 res;
            uint32_t* q0 = reinterpret_cast<uint32_t*>(&r0);
            uint32_t* q1 = reinterpret_cast<uint32_t*>(&r1);
            uint32_t* q2 = reinterpret_cast<uint32_t*>(&r2);
            uint32_t* q3 = reinterpret_cast<uint32_t*>(&r3);
            uint32_t* qr = reinterpret_cast<uint32_t*>(&res);
#pragma unroll
            for (int j = 0; j < 4; j++) {
                float2 f0 = __half22float2(*reinterpret_cast<__half2*>(&q0[j]));
                float2 f1 = __half22float2(*reinterpret_cast<__half2*>(&q1[j]));
                float2 f2 = __half22float2(*reinterpret_cast<__half2*>(&q2[j]));
                float2 f3 = __half22float2(*reinterpret_cast<__half2*>(&q3[j]));
                float vx = wt.x * f0.x + wt.y * f1.x + wt.z * f2.x + wt.w * f3.x;
                float vy = wt.x * f0.y + wt.y * f1.y + wt.z * f2.y + wt.w * f3.y;
                __half2 h = __floats2half2_rn(vx, vy);
                qr[j] = *reinterpret_cast<uint32_t*>(&h);
            }
            *reinterpret_cast<uint4*>(base + m * AROW + (l8 << 4)) = res;
        }
    };

    const int mbase = (wid >> 1) * 16;
    const int n0    = (wid & 1) * 64;
    float acc[8][4];
#pragma unroll
    for (int j = 0; j < 8; j++)
#pragma unroll
        for (int q = 0; q < 4; q++) acc[j][q] = 0.f;

    // mma over one chunk: A frags via ldsm, B frags LDG-direct from L2
    auto mma_chunk = [&](int st, int ch) {
        const uint32_t aT = sb + A_OFF(st);
        const uint32_t aoff = (uint32_t)(mbase + (lane & 15)) * AROW
                            + ((uint32_t)(lane >> 4) << 4);
        const uint4* gb = g_wbF + ch * 1024 + ((n0 >> 6) << 9) + lane;
#pragma unroll
        for (int s = 0; s < 4; s++) {
            uint32_t Ah[4];
            ldsm4(aT + aoff + s * 32, Ah);
#pragma unroll
            for (int p = 0; p < 4; p++) {
                uint4 bv = gb[(s << 7) + (p << 5)];
                const uint32_t* bq = reinterpret_cast<const uint32_t*>(&bv);
                mma16816(acc[p * 2],     Ah, bq);
                mma16816(acc[p * 2 + 1], Ah, bq + 2);
            }
        }
    };

    // ---- prologue: fill stage 0 ----
    gatherA(0, 0);
    PAIR_BAR(pair);

    // ---- main loop: pairs run independently; one named barrier per chunk ----
    const bool gfirst = wid & 1;
    for (int ch = 0; ch < NCHUNK; ch++) {
        int cur = ch & 1, nxt = cur ^ 1;
        if (gfirst) {
            if (ch + 1 < NCHUNK) gatherA(nxt, ch + 1);
            mma_chunk(cur, ch);
        } else {
            mma_chunk(cur, ch);
            if (ch + 1 < NCHUNK) gatherA(nxt, ch + 1);
        }
        PAIR_BAR(pair);
    }
    __syncthreads();

    // ---- epilogue: stage tile in smem, coalesced stores ----
    float* etile = reinterpret_cast<float*>(smem);  // [128 n][EROW] floats
#pragma unroll
    for (int nt = 0; nt < 8; nt++) {
        int n = n0 + nt * 8 + (lane & 3) * 2;
        float bv0 = __ldg(bias + n);
        float bv1 = __ldg(bias + n + 1);
        int mr = mbase + (lane >> 2);
        etile[n * EROW + mr]           = acc[nt][0] + bv0;
        etile[(n + 1) * EROW + mr]     = acc[nt][1] + bv1;
        etile[n * EROW + mr + 8]       = acc[nt][2] + bv0;
        etile[(n + 1) * EROW + mr + 8] = acc[nt][3] + bv1;
    }
    __syncthreads();
    {
        const int m4 = (tid & 15) * 4;
        const int nb = tid >> 4;
        float* ob = out + (size_t)b * OO * HW + hw0;
#pragma unroll
        for (int i = 0; i < 8; i++) {
            int n = i * 16 + nb;
            float4 v = *reinterpret_cast<const float4*>(etile + n * EROW + m4);
            *reinterpret_cast<float4*>(ob + (size_t)n * HW + m4) = v;
        }
    }
}

// ---------------------------------------------------------------------------
extern "C" void kernel_launch(void* const* d_in, const int* in_sizes, int n_in,
                              void* d_out, int out_size)
{
    const float* x      = (const float*)d_in[0];
    const float* offset = (const float*)d_in[1];
    const float* weight = (const float*)d_in[2];
    const float* bias   = (const float*)d_in[3];
    float* out = (float*)d_out;

    cudaFuncSetAttribute(dcn_mma_kernel,
                         cudaFuncAttributeMaxDynamicSharedMemorySize, SMEM_TOTAL);

    dim3 g1(128 + 5, 2, BB), b1(32, 8);
    prep_kernel<<<g1, b1>>>(x, weight);

    dcn_mma_kernel<<<512, 256, SMEM_TOTAL>>>(offset, bias, out);
}

// round 15
// speedup vs baseline: 1.2877x; 1.2877x over previous
#include <cuda_runtime.h>
#include <cuda_fp16.h>
#include <cstdint>

// Problem constants: B=8, C=128, H=W=64, O=128, 3x3, stride 1, pad 1, dil 1
#define BB 8
#define CC 128
#define HH 64
#define WW 64
#define OO 128
#define KTAP 9
#define HW (HH*WW)          // 4096
#define CK (CC*KTAP)        // 1152
#define NCHUNK 18           // CK / 64

// Scratch
__device__ __half g_xTh[BB*HH*WW*CC];   // [b][h][w][c] fp16, 8 MB
// B in fragment-major layout: [ch(18)][half(2)][s(4)][p(4)][lane(32)] x uint4
__device__ uint4 g_wbF[NCHUNK*1024];    // 288 KB

// ---------------------------------------------------------------------------
// SMEM: A stages (rows padded to 144 B) + bilinear param tables
// ---------------------------------------------------------------------------
#define AROW 144
#define ATILE (128*AROW)            // 18432
#define A_OFF(st) ((st)*ATILE)
#define SM_IDX (2*ATILE)            // 36864, [9][128] int4
#define SM_WT  (SM_IDX + 9*128*4*4) // 55296, [9][128] uint4 (4x half2 bcast weights)
#define SMEM_TOTAL (SM_WT + 9*128*4*4)  // 73728
#define EROW 132                    // epilogue smem row pitch (floats)

__device__ __forceinline__ uint32_t smem_u32(const void* p) {
    uint32_t a;
    asm("{ .reg .u64 t; cvta.to.shared.u64 t, %1; cvt.u32.u64 %0, t; }" : "=r"(a) : "l"(p));
    return a;
}
__device__ __forceinline__ void ldsm4(uint32_t addr, uint32_t* r) {
    asm volatile("ldmatrix.sync.aligned.m8n8.x4.shared.b16 {%0,%1,%2,%3}, [%4];"
                 : "=r"(r[0]), "=r"(r[1]), "=r"(r[2]), "=r"(r[3]) : "r"(addr));
}
__device__ __forceinline__ void mma16816(float* d, const uint32_t* a, const uint32_t* b) {
    asm volatile("mma.sync.aligned.m16n8k16.row.col.f32.f16.f16.f32 "
                 "{%0,%1,%2,%3}, {%4,%5,%6,%7}, {%8,%9}, {%0,%1,%2,%3};"
                 : "+f"(d[0]), "+f"(d[1]), "+f"(d[2]), "+f"(d[3])
                 : "r"(a[0]), "r"(a[1]), "r"(a[2]), "r"(a[3]), "r"(b[0]), "r"(b[1]));
}
#define PAIR_BAR(pid) asm volatile("bar.sync %0, 64;" :: "r"(1 + (pid)) : "memory")

// ---------------------------------------------------------------------------
// Kernel 1 (fused prep): blockIdx.x < 128 -> xpose tile; else -> wprep frag
// grid (128+5, 2, 8), block (32,8)
// ---------------------------------------------------------------------------
__global__ void prep_kernel(const float* __restrict__ x, const float* __restrict__ w) {
    if (blockIdx.x < 128) {
        __shared__ float tile[64][33];
        int b   = blockIdx.z;
        int hw0 = blockIdx.x * 32;
        int c0  = blockIdx.y * 64;
        const float* xb = x + (size_t)b * CC * HW;
#pragma unroll
        for (int j = 0; j < 64; j += 8)
            tile[threadIdx.y + j][threadIdx.x] =
                xb[(size_t)(c0 + threadIdx.y + j) * HW + hw0 + threadIdx.x];
        __syncthreads();
        __half* ob = g_xTh + (size_t)b * HW * CC + c0;
#pragma unroll
        for (int j = 0; j < 32; j += 8) {
            int row = threadIdx.y + j;
            __half2 h = __floats2half2_rn(tile[threadIdx.x * 2][row],
                                          tile[threadIdx.x * 2 + 1][row]);
            *reinterpret_cast<__half2*>(ob + (size_t)(hw0 + row) * CC + threadIdx.x * 2) = h;
        }
    } else {
        // weight [O,C,3,3] -> fragment-major B: one uint4 (8 fp16) per thread
        int slice = (blockIdx.x - 128) * 16 + blockIdx.z * 2 + blockIdx.y;  // 0..79
        int idx = slice * 256 + threadIdx.y * 32 + threadIdx.x;
        if (idx >= NCHUNK * 1024) return;
        int lane = idx & 31;
        int p    = (idx >> 5) & 3;
        int s    = (idx >> 7) & 3;
        int h    = (idx >> 9) & 1;
        int ch   = idx >> 10;
        int tap  = ch >> 1;
        int cbase = (ch & 1) << 6;
        uint32_t regs[4];
#pragma unroll
        for (int j = 0; j < 4; j++) {
            int o  = h * 64 + p * 16 + (lane >> 2) + ((j >> 1) << 3);
            int k0 = s * 16 + ((lane & 3) << 1) + ((j & 1) << 3);
            float v0 = w[(size_t)o * CK + (cbase + k0) * KTAP + tap];
            float v1 = w[(size_t)o * CK + (cbase + k0 + 1) * KTAP + tap];
            __half2 hh = __floats2half2_rn(v0, v1);
            regs[j] = *reinterpret_cast<uint32_t*>(&hh);
        }
        g_wbF[idx] = make_uint4(regs[0], regs[1], regs[2], regs[3]);
    }
}

// ---------------------------------------------------------------------------
// Kernel 2: fused gather + mma.sync fp16 GEMM; half2 bilinear combine;
// B fragments LDG-direct from L2; warp-pairs decoupled via named barriers.
// grid = 256, 256 threads, 2 CTAs/SM
// ---------------------------------------------------------------------------
__global__ void __launch_bounds__(256, 2) dcn_mma_kernel(
    const float* __restrict__ offset,
    const float* __restrict__ bias,
    float* __restrict__ out)
{
    extern __shared__ char smem[];
    const uint32_t sb = smem_u32(smem);
    const int tid  = threadIdx.x;
    const int wid  = tid >> 5;
    const int lane = tid & 31;
    const int pair = wid >> 1;
    const int b    = blockIdx.x >> 5;
    const int ho0  = (blockIdx.x & 31) * 2;
    const int hw0  = (blockIdx.x & 31) * 128;

    int*      sIdx = reinterpret_cast<int*>(smem + SM_IDX);
    uint32_t* sWtH = reinterpret_cast<uint32_t*>(smem + SM_WT);

    // ---- precompute bilinear params (idx + half2-broadcast weights) ----
    for (int p = tid; p < KTAP * 128; p += 256) {
        int m = p & 127;
        int k = p >> 7;
        int ho = ho0 + (m >> 6), wo = m & 63;
        float dy = offset[(((size_t)b * 18 + 2 * k    ) * 64 + ho) * 64 + wo];
        float dx = offset[(((size_t)b * 18 + 2 * k + 1) * 64 + ho) * 64 + wo];
        float py = (float)(ho - 1 + k / 3) + dy;
        float px = (float)(wo - 1 + k % 3) + dx;
        float y0f = floorf(py), x0f = floorf(px);
        int   y0 = (int)y0f,    x0 = (int)x0f;
        float ly = py - y0f, lx = px - x0f;
        float w4[4] = { (1.f - ly) * (1.f - lx), (1.f - ly) * lx,
                        ly * (1.f - lx),         ly * lx };
#pragma unroll
        for (int i = 0; i < 4; i++) {
            int yy = y0 + (i >> 1);
            int xx = x0 + (i & 1);
            bool v = (yy >= 0) & (yy < HH) & (xx >= 0) & (xx < WW);
            __half2 hw2 = __half2half2(__float2half(v ? w4[i] : 0.f));
            sWtH[p * 4 + i] = *reinterpret_cast<uint32_t*>(&hw2);
            sIdx[p * 4 + i] = v ? (((b * HH + yy) * WW + xx) * CC) : 0;
        }
    }
    __syncthreads();

    // warp-coalesced fp16 bilinear gather (pure half2 math)
    const int sub4 = lane >> 3;
    const int l8   = lane & 7;
    auto gatherA = [&](int st, int ch) {
        const int k   = ch >> 1;
        const int cc  = ((ch & 1) << 6) + (l8 << 3);
        char* base = smem + A_OFF(st);
#pragma unroll
        for (int p = 0; p < 4; p++) {
            int m = (wid << 4) + (p << 2) + sub4;
            const int4  id = *reinterpret_cast<const int4*>(sIdx + ((k << 7) + m) * 4);
            const uint4 wt = *reinterpret_cast<const uint4*>(sWtH + ((k << 7) + m) * 4);
            const __half2 wx = *reinterpret_cast<const __half2*>(&wt.x);
            const __half2 wy = *reinterpret_cast<const __half2*>(&wt.y);
            const __half2 wz = *reinterpret_cast<const __half2*>(&wt.z);
            const __half2 ww = *reinterpret_cast<const __half2*>(&wt.w);
            uint4 r0 = *reinterpret_cast<const uint4*>(g_xTh + id.x + cc);
            uint4 r1 = *reinterpret_cast<const uint4*>(g_xTh + id.y + cc);
            uint4 r2 = *reinterpret_cast<const uint4*>(g_xTh + id.z + cc);
            uint4 r3 = *reinterpret_cast<const uint4*>(g_xTh + id.w + cc);
            uint4 res;
            const uint32_t* q0 = reinterpret_cast<const uint32_t*>(&r0);
            const uint32_t* q1 = reinterpret_cast<const uint32_t*>(&r1);
            const uint32_t* q2 = reinterpret_cast<const uint32_t*>(&r2);
            const uint32_t* q3 = reinterpret_cast<const uint32_t*>(&r3);
            uint32_t* qr = reinterpret_cast<uint32_t*>(&res);
#pragma unroll
            for (int j = 0; j < 4; j++) {
                __half2 h0 = *reinterpret_cast<const __half2*>(&q0[j]);
                __half2 h1 = *reinterpret_cast<const __half2*>(&q1[j]);
                __half2 h2 = *reinterpret_cast<const __half2*>(&q2[j]);
                __half2 h3 = *reinterpret_cast<const __half2*>(&q3[j]);
                __half2 t0 = __hfma2(h1, wy, __hmul2(h0, wx));
                __half2 t1 = __hfma2(h3, ww, __hmul2(h2, wz));
                __half2 r  = __hadd2(t0, t1);
                qr[j] = *reinterpret_cast<uint32_t*>(&r);
            }
            *reinterpret_cast<uint4*>(base + m * AROW + (l8 << 4)) = res;
        }
    };

    const int mbase = (wid >> 1) * 32;
    const int n0    = (wid & 1) * 64;
    float acc[2][8][4];
#pragma unroll
    for (int i = 0; i < 2; i++)
#pragma unroll
        for (int j = 0; j < 8; j++)
#pragma unroll
            for (int q = 0; q < 4; q++) acc[i][j][q] = 0.f;

    // mma over one chunk: A frags via ldsm, B frags LDG-direct (double-buffered)
    auto mma_chunk = [&](int st, int ch) {
        const uint32_t aT = sb + A_OFF(st);
        const uint32_t aoff = (uint32_t)(lane & 15) * AROW + ((uint32_t)(lane >> 4) << 4);
        const uint4* gb = g_wbF + ch * 1024 + ((n0 >> 6) << 9) + lane;
        uint4 Bv[2][4];
#pragma unroll
        for (int p = 0; p < 4; p++) Bv[0][p] = gb[p << 5];
#pragma unroll
        for (int s = 0; s < 4; s++) {
            const int cu = s & 1, nx = cu ^ 1;
            if (s < 3) {
#pragma unroll
                for (int p = 0; p < 4; p++) Bv[nx][p] = gb[((s + 1) << 7) + (p << 5)];
            }
            uint32_t Ah[2][4];
#pragma unroll
            for (int mt = 0; mt < 2; mt++)
                ldsm4(aT + aoff + (mbase + mt * 16) * AROW + s * 32, Ah[mt]);
#pragma unroll
            for (int p = 0; p < 4; p++) {
                const uint32_t* bq = reinterpret_cast<const uint32_t*>(&Bv[cu][p]);
#pragma unroll
                for (int mt = 0; mt < 2; mt++) {
                    mma16816(acc[mt][p * 2],     Ah[mt], bq);
                    mma16816(acc[mt][p * 2 + 1], Ah[mt], bq + 2);
                }
            }
        }
    };

    // ---- prologue: fill stage 0 ----
    gatherA(0, 0);
    PAIR_BAR(pair);

    // ---- main loop: pairs run independently; one named barrier per chunk ----
    const bool gfirst = wid & 1;
    for (int ch = 0; ch < NCHUNK; ch++) {
        int cur = ch & 1, nxt = cur ^ 1;
        if (gfirst) {
            if (ch + 1 < NCHUNK) gatherA(nxt, ch + 1);
            mma_chunk(cur, ch);
        } else {
            mma_chunk(cur, ch);
            if (ch + 1 < NCHUNK) gatherA(nxt, ch + 1);
        }
        PAIR_BAR(pair);
    }
    __syncthreads();

    // ---- epilogue: stage tile in smem, coalesced stores ----
    float* etile = reinterpret_cast<float*>(smem);  // [128 n][EROW] floats
#pragma unroll
    for (int nt = 0; nt < 8; nt++) {
        int n = n0 + nt * 8 + (lane & 3) * 2;
        float bv0 = __ldg(bias + n);
        float bv1 = __ldg(bias + n + 1);
#pragma unroll
        for (int mt = 0; mt < 2; mt++) {
            int mr = mbase + mt * 16 + (lane >> 2);
            etile[n * EROW + mr]           = acc[mt][nt][0] + bv0;
            etile[(n + 1) * EROW + mr]     = acc[mt][nt][1] + bv1;
            etile[n * EROW + mr + 8]       = acc[mt][nt][2] + bv0;
            etile[(n + 1) * EROW + mr + 8] = acc[mt][nt][3] + bv1;
        }
    }
    __syncthreads();
    {
        const int m4 = (tid & 31) * 4;
        const int nb = tid >> 5;
        float* ob = out + (size_t)b * OO * HW + hw0;
#pragma unroll
        for (int i = 0; i < 16; i++) {
            int n = i * 8 + nb;
            float4 v = *reinterpret_cast<const float4*>(etile + n * EROW + m4);
            *reinterpret_cast<float4*>(ob + (size_t)n * HW + m4) = v;
        }
    }
}

// ---------------------------------------------------------------------------
extern "C" void kernel_launch(void* const* d_in, const int* in_sizes, int n_in,
                              void* d_out, int out_size)
{
    const float* x      = (const float*)d_in[0];
    const float* offset = (const float*)d_in[1];
    const float* weight = (const float*)d_in[2];
    const float* bias   = (const float*)d_in[3];
    float* out = (float*)d_out;

    cudaFuncSetAttribute(dcn_mma_kernel,
                         cudaFuncAttributeMaxDynamicSharedMemorySize, SMEM_TOTAL);

    dim3 g1(128 + 5, 2, BB), b1(32, 8);
    prep_kernel<<<g1, b1>>>(x, weight);

    dcn_mma_kernel<<<256, 256, SMEM_TOTAL>>>(offset, bias, out);
}